// round 11
// baseline (speedup 1.0000x reference)
#include <cuda_runtime.h>
#include <cuda_bf16.h>
#include <math.h>
#include <stdint.h>

#define BB   4
#define CIN  32
#define COUT 64
#define HH   32
#define WW   32
#define HP   34
#define WP   34
#define CF   128            // CIN * 4 trig features = K
#define NT   32             // M tiles: 4 b x 8 row-blocks (4 rows x 32 cols = 128 px)
#define KP   136            // padded smem row stride in bf16 (272B, conflict-free LDSM)
#define TILE_SMEM (128 * KP * 2)   // 34816 B per operand tile

#define FEAT_TOTAL (BB * HP * WP * CIN)   // 147968
#define WGT_TOTAL  (9 * COUT * CIN)       // 18432

// ---------------- device scratch (no allocs allowed) ----------------
__device__ __nv_bfloat16 g_featH[BB * HP * WP * CF];   // padded NHWC, hi part
__device__ __nv_bfloat16 g_featL[BB * HP * WP * CF];   // lo part
__device__ __nv_bfloat16 g_Bh[9][128 * 128];           // weights hi: [tap][n][k] row-major
__device__ __nv_bfloat16 g_Bl[9][128 * 128];           // weights lo
__device__ float g_part[9][NT][128][128];              // [tap][tile][m][n] fp32 partials (18.9MB)

// ---------------- PTX helpers (sm_80-era; compile for compute_103) ------------
__device__ __forceinline__ uint32_t smem_u32(const void* p) {
    uint32_t a;
    asm("{ .reg .u64 t; cvta.to.shared.u64 t, %1; cvt.u32.u64 %0, t; }" : "=r"(a) : "l"(p));
    return a;
}
#define LDSM_X4(r0, r1, r2, r3, addr) \
    asm volatile("ldmatrix.sync.aligned.m8n8.x4.shared.b16 {%0,%1,%2,%3}, [%4];" \
        : "=r"(r0), "=r"(r1), "=r"(r2), "=r"(r3) : "r"(addr))
#define MMA16816(c, a0, a1, a2, a3, b0, b1) \
    asm volatile("mma.sync.aligned.m16n8k16.row.col.f32.bf16.bf16.f32 " \
        "{%0,%1,%2,%3}, {%4,%5,%6,%7}, {%8,%9}, {%0,%1,%2,%3};" \
        : "+f"((c)[0]), "+f"((c)[1]), "+f"((c)[2]), "+f"((c)[3]) \
        : "r"(a0), "r"(a1), "r"(a2), "r"(a3), "r"(b0), "r"(b1))

// ---------------- prep: trig features (hi/lo bf16) + folded weight matrices ----
// cos^3(x-p) = 3/4[cx*cp + sx*sp] + 1/4[c3x*c3p + s3x*s3p]
__global__ void prep_kernel(const float* __restrict__ x,
                            const float* __restrict__ probe,
                            const float* __restrict__ outw) {
    int i = blockIdx.x * blockDim.x + threadIdx.x;
    if (i < FEAT_TOTAL) {
        int c = i & 31;
        int t = i >> 5;
        int pc = t % WP; t /= WP;
        int pr = t % HP;
        int b  = t / HP;
        float v = 0.0f;  // zero-pad applied BEFORE cos in the reference
        if (pr >= 1 && pr <= HH && pc >= 1 && pc <= WW)
            v = x[((b * CIN + c) * HH + (pr - 1)) * WW + (pc - 1)];
        float s, cv;
        __sincosf(v, &s, &cv);    // fast-path trig; abs err ~5e-7 << bf16 term err
        float f[4];
        f[0] = cv; f[1] = s;
        f[2] = cv * (4.0f * cv * cv - 3.0f);
        f[3] = s * (3.0f - 4.0f * s * s);
        int base = ((b * HP + pr) * WP + pc) * CF + c * 4;
        #pragma unroll
        for (int q = 0; q < 4; q++) {
            float a = f[q];
            __nv_bfloat16 h = __float2bfloat16(a);
            g_featH[base + q] = h;
            g_featL[base + q] = __float2bfloat16(a - __bfloat162float(h));
        }
    } else {
        int j = i - FEAT_TOTAL;
        if (j >= WGT_TOTAL) return;
        int c  = j % CIN;
        int o  = (j / CIN) % COUT;
        int kl = j / (CIN * COUT);
        int widx = (c * COUT + o) * 9 + kl;   // (1,CIN,COUT,1,1,3,3) flat

        float sp, cp, sw, cw;
        sincosf(probe[widx], &sp, &cp);
        sincosf(outw[widx],  &sw, &cw);
        float c3p = cp * (4.0f * cp * cp - 3.0f);
        float s3p = sp * (3.0f - 4.0f * sp * sp);
        float wx[4] = {0.75f * cw * cp, 0.75f * cw * sp, 0.25f * cw * c3p, 0.25f * cw * s3p};
        float wy[4] = {0.75f * sw * cp, 0.75f * sw * sp, 0.25f * sw * c3p, 0.25f * sw * s3p};

        #pragma unroll
        for (int f = 0; f < 4; f++) {
            int col = c * 4 + f;
            {
                float a = wx[f];
                __nv_bfloat16 h = __float2bfloat16(a);
                g_Bh[kl][o * 128 + col] = h;
                g_Bl[kl][o * 128 + col] = __float2bfloat16(a - __bfloat162float(h));
            }
            {
                float a = wy[f];
                __nv_bfloat16 h = __float2bfloat16(a);
                g_Bh[kl][(o + 64) * 128 + col] = h;
                g_Bl[kl][(o + 64) * 128 + col] = __float2bfloat16(a - __bfloat162float(h));
            }
        }
    }
}

// ---------------- gemm: per-CTA (M-tile, single tap) -> fp32 partial D ---------
// 256 threads = 8 warps arranged 2(m) x 4(n): warp owns m64 x n32.
// smem: Ah | Al | Bh | Bl, each 128 rows x KP bf16 (row stride 272B).
__global__ __launch_bounds__(256) void gemm_kernel() {
    extern __shared__ unsigned char smem[];
    unsigned char* sAh = smem;
    unsigned char* sAl = smem + TILE_SMEM;
    unsigned char* sBh = smem + 2 * TILE_SMEM;
    unsigned char* sBl = smem + 3 * TILE_SMEM;
    const uint32_t uAh = smem_u32(sAh);
    const uint32_t uAl = uAh + TILE_SMEM;
    const uint32_t uBh = uAh + 2 * TILE_SMEM;
    const uint32_t uBl = uAh + 3 * TILE_SMEM;

    const int tid  = threadIdx.x;
    const int wid  = tid >> 5;
    const int ln   = tid & 31;
    const int tile = blockIdx.x;          // 0..31
    const int kl   = blockIdx.y;          // 0..8 (tap)
    const int k = kl / 3, l = kl % 3;
    const int b    = tile >> 3;
    const int r0   = (tile & 7) * 4;

    const int mgrp = wid >> 2;            // 0..1 -> m base = mgrp*64
    const int ngrp = wid & 3;             // 0..3 -> n base = ngrp*32
    const int mb   = mgrp * 64;
    const int nb   = ngrp * 32;

    // ldmatrix lane addressing (K-major, non-trans)
    const uint32_t arow = (uint32_t)(ln & 15);
    const uint32_t acol = (uint32_t)((ln >> 4) * 8);
    const int brow = (ln & 7) + ((ln >> 4) & 1) * 8;
    const int bcol = ((ln >> 3) & 1) * 8;

    // stage: 2048 16B-chunks per operand tile
    for (int i = tid; i < 2048; i += 256) {
        int m = i >> 4, j = i & 15;
        uint32_t doff = (uint32_t)(m * (KP * 2) + j * 16);
        size_t abyte = ((size_t)((b * HP + (r0 + (m >> 5) + k)) * WP + ((m & 31) + l)) * CF + j * 8) * 2;
        *(uint4*)(sAh + doff) = *(const uint4*)((const unsigned char*)g_featH + abyte);
        *(uint4*)(sAl + doff) = *(const uint4*)((const unsigned char*)g_featL + abyte);
        size_t bbyte = ((size_t)m * 128 + j * 8) * 2;
        *(uint4*)(sBh + doff) = *(const uint4*)((const unsigned char*)g_Bh[kl] + bbyte);
        *(uint4*)(sBl + doff) = *(const uint4*)((const unsigned char*)g_Bl[kl] + bbyte);
    }
    __syncthreads();

    float c[4][4][4];   // [mf][n8][quad]
    #pragma unroll
    for (int mf = 0; mf < 4; mf++)
        #pragma unroll
        for (int nf = 0; nf < 4; nf++)
            #pragma unroll
            for (int q = 0; q < 4; q++) c[mf][nf][q] = 0.0f;

    #pragma unroll
    for (int ks = 0; ks < 8; ks++) {
        const uint32_t ka = (uint32_t)(ks * 32);   // 16 bf16 = 32B
        uint32_t ah[4][4], al[4][4];
        #pragma unroll
        for (int mf = 0; mf < 4; mf++) {
            const uint32_t aoff = (uint32_t)(((mb + mf * 16 + arow) * KP) * 2) + acol * 2 + ka;
            LDSM_X4(ah[mf][0], ah[mf][1], ah[mf][2], ah[mf][3], uAh + aoff);
            LDSM_X4(al[mf][0], al[mf][1], al[mf][2], al[mf][3], uAl + aoff);
        }
        uint32_t bh[2][4], bl[2][4];
        #pragma unroll
        for (int g = 0; g < 2; g++) {
            const uint32_t boff = (uint32_t)(((nb + g * 16 + brow) * KP + bcol) * 2) + ka;
            LDSM_X4(bh[g][0], bh[g][1], bh[g][2], bh[g][3], uBh + boff);
            LDSM_X4(bl[g][0], bl[g][1], bl[g][2], bl[g][3], uBl + boff);
        }
        #pragma unroll
        for (int mf = 0; mf < 4; mf++) {
            #pragma unroll
            for (int nf = 0; nf < 4; nf++) {
                const int g = nf >> 1, h2 = (nf & 1) * 2;
                MMA16816(c[mf][nf], ah[mf][0], ah[mf][1], ah[mf][2], ah[mf][3], bh[g][h2], bh[g][h2 + 1]);
                MMA16816(c[mf][nf], al[mf][0], al[mf][1], al[mf][2], al[mf][3], bh[g][h2], bh[g][h2 + 1]);
                MMA16816(c[mf][nf], ah[mf][0], ah[mf][1], ah[mf][2], ah[mf][3], bl[g][h2], bl[g][h2 + 1]);
            }
        }
    }

    // epilogue: D frag -> g_part[kl][tile][m][n]
    float* dst = &g_part[kl][tile][0][0];
    const int row = ln >> 2;
    const int colb = (ln & 3) * 2;
    #pragma unroll
    for (int mf = 0; mf < 4; mf++) {
        #pragma unroll
        for (int nf = 0; nf < 4; nf++) {
            const int n0 = nb + nf * 8 + colb;
            const int m1 = mb + mf * 16 + row;
            *(float2*)&dst[m1 * 128 + n0]       = make_float2(c[mf][nf][0], c[mf][nf][1]);
            *(float2*)&dst[(m1 + 8) * 128 + n0] = make_float2(c[mf][nf][2], c[mf][nf][3]);
        }
    }
}

// ---------------- combine: sum 9 partials + atan2 (smem transpose) ------------
__global__ __launch_bounds__(256) void combine_kernel(float* __restrict__ out) {
    __shared__ float s_x[128][65];
    __shared__ float s_y[128][65];
    const int t = blockIdx.x;
    const int tid = threadIdx.x;

    for (int i = tid; i < 128 * 128; i += 256) {
        float v = 0.0f;
        #pragma unroll
        for (int g = 0; g < 9; g++) v += g_part[g][t][0][i];
        int m = i >> 7, n = i & 127;
        if (n < 64) s_x[m][n] = v;
        else        s_y[m][n - 64] = v;
    }
    __syncthreads();

    const int b = t >> 3;
    const int hbase = (t & 7) * 4;
    for (int i = tid; i < 64 * 128; i += 256) {
        int o = i >> 7, m = i & 127;
        float ang = atan2f(s_y[m][o], s_x[m][o]);
        int h = hbase + (m >> 5), w = m & 31;
        out[((b * COUT + o) * HH + h) * WW + w] = ang;
    }
}

// ---------------- launch ----------------
extern "C" void kernel_launch(void* const* d_in, const int* in_sizes, int n_in,
                              void* d_out, int out_size) {
    const float* x     = (const float*)d_in[0];
    const float* probe = (const float*)d_in[1];
    const float* outw  = (const float*)d_in[2];
    float* out = (float*)d_out;

    const int SMEM = 4 * TILE_SMEM;   // 139264 B
    cudaFuncSetAttribute(gemm_kernel, cudaFuncAttributeMaxDynamicSharedMemorySize, SMEM);

    {
        const int total = FEAT_TOTAL + WGT_TOTAL;
        prep_kernel<<<(total + 255) / 256, 256>>>(x, probe, outw);
    }
    {
        dim3 grid(NT, 9);
        gemm_kernel<<<grid, 256, SMEM>>>();
    }
    combine_kernel<<<NT, 256>>>(out);
    (void)in_sizes; (void)n_in; (void)out_size;
}

// round 15
// speedup vs baseline: 1.1376x; 1.1376x over previous
#include <cuda_runtime.h>
#include <cuda_bf16.h>
#include <math.h>
#include <stdint.h>

#define BB   4
#define CIN  32
#define COUT 64
#define HH   32
#define WW   32
#define HP   34
#define WP   34
#define CF   128            // CIN*4 trig features = K per tap
#define NT   32             // M tiles: 4 b x 8 row-blocks (4 rows x 32 cols = 128 px)
#define NGRP 3
#define KH   64             // K-half in bf16
#define KP2  72             // padded row stride (144B): LDSM + STS conflict-free
#define HT_BYTES (128 * KP2 * 2)      // 18432 B per half-tile
#define CHUNK_BYTES (4 * HT_BYTES)    // 73728 B (Ah|Al|Bh|Bl)

#define FEAT_TOTAL (BB * HP * WP * CIN)   // 147968
#define WGT_TOTAL  (9 * COUT * CIN)       // 18432

// ---------------- device scratch ----------------
__device__ __nv_bfloat16 g_featH[BB * HP * WP * CF];   // padded NHWC, hi
__device__ __nv_bfloat16 g_featL[BB * HP * WP * CF];   // lo
__device__ __nv_bfloat16 g_Bh[9][128 * 128];           // [tap][n][k]
__device__ __nv_bfloat16 g_Bl[9][128 * 128];
__device__ float g_part[NGRP][NT][128][128];           // fp32 partials (6.3MB)

// ---------------- PTX helpers ----------------
__device__ __forceinline__ uint32_t smem_u32(const void* p) {
    uint32_t a;
    asm("{ .reg .u64 t; cvta.to.shared.u64 t, %1; cvt.u32.u64 %0, t; }" : "=r"(a) : "l"(p));
    return a;
}
#define CP_ASYNC16(dst, src) \
    asm volatile("cp.async.cg.shared.global [%0], [%1], 16;" :: "r"(dst), "l"(src))
#define CP_COMMIT() asm volatile("cp.async.commit_group;" ::: "memory")
#define CP_WAIT1()  asm volatile("cp.async.wait_group 1;" ::: "memory")
#define CP_WAIT0()  asm volatile("cp.async.wait_group 0;" ::: "memory")
#define LDSM_X4(r0, r1, r2, r3, addr) \
    asm volatile("ldmatrix.sync.aligned.m8n8.x4.shared.b16 {%0,%1,%2,%3}, [%4];" \
        : "=r"(r0), "=r"(r1), "=r"(r2), "=r"(r3) : "r"(addr))
#define MMA16816(c, a0, a1, a2, a3, b0, b1) \
    asm volatile("mma.sync.aligned.m16n8k16.row.col.f32.bf16.bf16.f32 " \
        "{%0,%1,%2,%3}, {%4,%5,%6,%7}, {%8,%9}, {%0,%1,%2,%3};" \
        : "+f"((c)[0]), "+f"((c)[1]), "+f"((c)[2]), "+f"((c)[3]) \
        : "r"(a0), "r"(a1), "r"(a2), "r"(a3), "r"(b0), "r"(b1))

__device__ __forceinline__ uint32_t pack_bf2(float a, float b) {
    __nv_bfloat162 v = __floats2bfloat162_rn(a, b);
    return *reinterpret_cast<uint32_t*>(&v);
}

// ---------------- prep ----------------
// cos^3(x-p) = 3/4[cx*cp + sx*sp] + 1/4[c3x*c3p + s3x*s3p]
__global__ void prep_kernel(const float* __restrict__ x,
                            const float* __restrict__ probe,
                            const float* __restrict__ outw) {
    int i = blockIdx.x * blockDim.x + threadIdx.x;
    if (i < FEAT_TOTAL) {
        int c = i & 31;
        int t = i >> 5;
        int pc = t % WP; t /= WP;
        int pr = t % HP;
        int b  = t / HP;
        float v = 0.0f;  // zero-pad BEFORE cos
        if (pr >= 1 && pr <= HH && pc >= 1 && pc <= WW)
            v = x[((b * CIN + c) * HH + (pr - 1)) * WW + (pc - 1)];
        float s, cv;
        sincosf(v, &s, &cv);
        float f[4];
        f[0] = cv; f[1] = s;
        f[2] = cv * (4.0f * cv * cv - 3.0f);
        f[3] = s * (3.0f - 4.0f * s * s);
        float h[4], lo[4];
        #pragma unroll
        for (int q = 0; q < 4; q++) {
            h[q]  = __bfloat162float(__float2bfloat16(f[q]));
            lo[q] = f[q] - h[q];
        }
        int base = ((b * HP + pr) * WP + pc) * CF + c * 4;   // 8B-aligned
        *reinterpret_cast<uint2*>(&g_featH[base]) =
            make_uint2(pack_bf2(h[0], h[1]), pack_bf2(h[2], h[3]));
        *reinterpret_cast<uint2*>(&g_featL[base]) =
            make_uint2(pack_bf2(lo[0], lo[1]), pack_bf2(lo[2], lo[3]));
    } else {
        int j = i - FEAT_TOTAL;
        if (j >= WGT_TOTAL) return;
        int c  = j % CIN;
        int o  = (j / CIN) % COUT;
        int kl = j / (CIN * COUT);
        int widx = (c * COUT + o) * 9 + kl;

        float sp, cp, sw, cw;
        sincosf(probe[widx], &sp, &cp);
        sincosf(outw[widx],  &sw, &cw);
        float c3p = cp * (4.0f * cp * cp - 3.0f);
        float s3p = sp * (3.0f - 4.0f * sp * sp);
        float wx[4] = {0.75f * cw * cp, 0.75f * cw * sp, 0.25f * cw * c3p, 0.25f * cw * s3p};
        float wy[4] = {0.75f * sw * cp, 0.75f * sw * sp, 0.25f * sw * c3p, 0.25f * sw * s3p};
        #pragma unroll
        for (int f = 0; f < 4; f++) {
            int col = c * 4 + f;
            float a = wx[f];
            __nv_bfloat16 hh = __float2bfloat16(a);
            g_Bh[kl][o * 128 + col] = hh;
            g_Bl[kl][o * 128 + col] = __float2bfloat16(a - __bfloat162float(hh));
            a = wy[f];
            hh = __float2bfloat16(a);
            g_Bh[kl][(o + 64) * 128 + col] = hh;
            g_Bl[kl][(o + 64) * 128 + col] = __float2bfloat16(a - __bfloat162float(hh));
        }
    }
}

// ---------------- gemm: (M-tile, tap-group) with cp.async double buffer -------
// 256 threads = 8 warps (2m x 4n), warp tile m64 x n32.
// chunk q (0..5): tap it=q>>1, khalf h=q&1.  Buffers alternate per chunk.
__global__ __launch_bounds__(256) void gemm_kernel() {
    extern __shared__ unsigned char smem[];
    const uint32_t u0 = smem_u32(smem);

    const int tid  = threadIdx.x;
    const int wid  = tid >> 5;
    const int ln   = tid & 31;
    const int tile = blockIdx.x;
    const int grp  = blockIdx.y;
    const int b    = tile >> 3;
    const int r0   = (tile & 7) * 4;

    const int mb = (wid >> 2) * 64;
    const int nb = (wid & 3) * 32;

    const uint32_t arow = (uint32_t)(ln & 15);
    const uint32_t acol = (uint32_t)((ln >> 4) * 8);
    const int brow = (ln & 7) + ((ln >> 4) & 1) * 8;
    const int bcol = ((ln >> 3) & 1) * 8;

    // ---- staging lambda-ish macro: issue cp.async for chunk q into buffer bu
    // per thread: 16 chunks of 16B (4 per operand)
    auto stage = [&](int q, int bu) {
        const int it = q >> 1, h = q & 1;
        const int kl = grp * 3 + it;
        const int k = kl / 3, l = kl % 3;
        const uint32_t bufb = u0 + (uint32_t)bu * CHUNK_BYTES;
        const unsigned char* srcA_H = (const unsigned char*)g_featH;
        const unsigned char* srcA_L = (const unsigned char*)g_featL;
        const unsigned char* srcB_H = (const unsigned char*)g_Bh[kl];
        const unsigned char* srcB_L = (const unsigned char*)g_Bl[kl];
        #pragma unroll
        for (int rep = 0; rep < 4; rep++) {
            int ch = rep * 256 + tid;          // 0..1023
            int m = ch >> 3, j = ch & 7;
            uint32_t doff = (uint32_t)(m * (KP2 * 2) + j * 16);
            // A source: pixel (b, r0+(m>>5)+k, (m&31)+l), khalf h
            size_t abyte = (size_t)((b * HP + (r0 + (m >> 5) + k)) * WP + ((m & 31) + l)) * 256
                           + (size_t)h * 128 + (size_t)j * 16;
            CP_ASYNC16(bufb + doff,                srcA_H + abyte);
            CP_ASYNC16(bufb + HT_BYTES + doff,     srcA_L + abyte);
            // B source: row n=m, khalf h
            size_t bbyte = (size_t)m * 256 + (size_t)h * 128 + (size_t)j * 16;
            CP_ASYNC16(bufb + 2 * HT_BYTES + doff, srcB_H + bbyte);
            CP_ASYNC16(bufb + 3 * HT_BYTES + doff, srcB_L + bbyte);
        }
        CP_COMMIT();
    };

    float c[4][4][4];
    #pragma unroll
    for (int mf = 0; mf < 4; mf++)
        #pragma unroll
        for (int nf = 0; nf < 4; nf++)
            #pragma unroll
            for (int q = 0; q < 4; q++) c[mf][nf][q] = 0.0f;

    stage(0, 0);   // prologue

    #pragma unroll
    for (int q = 0; q < 6; q++) {
        if (q + 1 < 6) { stage(q + 1, (q + 1) & 1); CP_WAIT1(); }
        else           { CP_WAIT0(); }
        __syncthreads();

        const uint32_t uAh = u0 + (uint32_t)(q & 1) * CHUNK_BYTES;
        const uint32_t uAl = uAh + HT_BYTES;
        const uint32_t uBh = uAh + 2 * HT_BYTES;
        const uint32_t uBl = uAh + 3 * HT_BYTES;

        #pragma unroll
        for (int ks = 0; ks < 4; ks++) {
            const uint32_t ka = (uint32_t)(ks * 32);
            uint32_t ah[4][4], al[4][4];
            #pragma unroll
            for (int mf = 0; mf < 4; mf++) {
                const uint32_t aoff = (uint32_t)((mb + mf * 16 + arow) * (KP2 * 2)) + acol * 2 + ka;
                LDSM_X4(ah[mf][0], ah[mf][1], ah[mf][2], ah[mf][3], uAh + aoff);
                LDSM_X4(al[mf][0], al[mf][1], al[mf][2], al[mf][3], uAl + aoff);
            }
            uint32_t bh[2][4], bl[2][4];
            #pragma unroll
            for (int g = 0; g < 2; g++) {
                const uint32_t boff = (uint32_t)(((nb + g * 16 + brow) * KP2 + bcol) * 2) + ka;
                LDSM_X4(bh[g][0], bh[g][1], bh[g][2], bh[g][3], uBh + boff);
                LDSM_X4(bl[g][0], bl[g][1], bl[g][2], bl[g][3], uBl + boff);
            }
            #pragma unroll
            for (int mf = 0; mf < 4; mf++) {
                #pragma unroll
                for (int nf = 0; nf < 4; nf++) {
                    const int g = nf >> 1, h2 = (nf & 1) * 2;
                    MMA16816(c[mf][nf], ah[mf][0], ah[mf][1], ah[mf][2], ah[mf][3], bh[g][h2], bh[g][h2 + 1]);
                    MMA16816(c[mf][nf], al[mf][0], al[mf][1], al[mf][2], al[mf][3], bh[g][h2], bh[g][h2 + 1]);
                    MMA16816(c[mf][nf], ah[mf][0], ah[mf][1], ah[mf][2], ah[mf][3], bl[g][h2], bl[g][h2 + 1]);
                }
            }
        }
        __syncthreads();   // all warps done reading this buffer before restage
    }

    float* dst = &g_part[grp][tile][0][0];
    const int row = ln >> 2;
    const int colb = (ln & 3) * 2;
    #pragma unroll
    for (int mf = 0; mf < 4; mf++) {
        #pragma unroll
        for (int nf = 0; nf < 4; nf++) {
            const int n0 = nb + nf * 8 + colb;
            const int m1 = mb + mf * 16 + row;
            *(float2*)&dst[m1 * 128 + n0]       = make_float2(c[mf][nf][0], c[mf][nf][1]);
            *(float2*)&dst[(m1 + 8) * 128 + n0] = make_float2(c[mf][nf][2], c[mf][nf][3]);
        }
    }
}

// ---------------- combine: sum 3 partials + atan2 ----------------
__global__ __launch_bounds__(256) void combine_kernel(float* __restrict__ out) {
    __shared__ float s_x[128][65];
    __shared__ float s_y[128][65];
    const int t = blockIdx.x;
    const int tid = threadIdx.x;

    for (int i = tid; i < 128 * 128; i += 256) {
        float v = g_part[0][t][0][i] + g_part[1][t][0][i] + g_part[2][t][0][i];
        int m = i >> 7, n = i & 127;
        if (n < 64) s_x[m][n] = v;
        else        s_y[m][n - 64] = v;
    }
    __syncthreads();

    const int b = t >> 3;
    const int hbase = (t & 7) * 4;
    for (int i = tid; i < 64 * 128; i += 256) {
        int o = i >> 7, m = i & 127;
        float ang = atan2f(s_y[m][o], s_x[m][o]);
        int h = hbase + (m >> 5), w = m & 31;
        out[((b * COUT + o) * HH + h) * WW + w] = ang;
    }
}

// ---------------- launch ----------------
extern "C" void kernel_launch(void* const* d_in, const int* in_sizes, int n_in,
                              void* d_out, int out_size) {
    const float* x     = (const float*)d_in[0];
    const float* probe = (const float*)d_in[1];
    const float* outw  = (const float*)d_in[2];
    float* out = (float*)d_out;

    const int SMEM = 2 * CHUNK_BYTES;   // 147456 B
    cudaFuncSetAttribute(gemm_kernel, cudaFuncAttributeMaxDynamicSharedMemorySize, SMEM);

    {
        const int total = FEAT_TOTAL + WGT_TOTAL;
        prep_kernel<<<(total + 255) / 256, 256>>>(x, probe, outw);
    }
    {
        dim3 grid(NT, NGRP);
        gemm_kernel<<<grid, 256, SMEM>>>();
    }
    combine_kernel<<<NT, 256>>>(out);
    (void)in_sizes; (void)n_in; (void)out_size;
}